// round 13
// baseline (speedup 1.0000x reference)
#include <cuda_runtime.h>
#include <cuda_fp16.h>
#include <cstdint>

#define BB 32
#define NN 512
#define CC 1024
#define HH 16
#define HD 64
#define SCALE 0.125f
#define LOG2E 1.44269504f
#define MTOT (BB * NN)   // 16384
#define CH (CC / 2)      // 512 packed half2 words per row

// packed-half2 scratch (uint32 = 2 fp16)
__device__ uint32_t g_xh[MTOT * CH];
__device__ uint32_t g_wqkvh[3 * CC * CH];
__device__ uint32_t g_wph[CC * CH];
__device__ uint32_t g_qh[BB * HH * NN * HD / 2];
__device__ uint32_t g_kh[BB * HH * NN * HD / 2];
__device__ uint32_t g_vh[BB * HH * NN * HD / 2];
__device__ uint32_t g_oh[MTOT * CH];

__device__ __forceinline__ uint32_t packh2(float a, float b) {
    __half2 h = __floats2half2_rn(a, b);
    return *(uint32_t*)&h;
}

__device__ __forceinline__ void mma16(float* d, const uint32_t* a, const uint32_t* b) {
    asm volatile(
        "mma.sync.aligned.m16n8k16.row.col.f32.f16.f16.f32 "
        "{%0,%1,%2,%3}, {%4,%5,%6,%7}, {%8,%9}, {%0,%1,%2,%3};"
        : "+f"(d[0]), "+f"(d[1]), "+f"(d[2]), "+f"(d[3])
        : "r"(a[0]), "r"(a[1]), "r"(a[2]), "r"(a[3]), "r"(b[0]), "r"(b[1]));
}

__device__ __forceinline__ void ldmx4(uint32_t* r, uint32_t addr) {
    asm volatile("ldmatrix.sync.aligned.m8n8.x4.shared.b16 {%0,%1,%2,%3}, [%4];"
                 : "=r"(r[0]), "=r"(r[1]), "=r"(r[2]), "=r"(r[3]) : "r"(addr));
}

__device__ __forceinline__ void ldmx4t(uint32_t* r, uint32_t addr) {
    asm volatile("ldmatrix.sync.aligned.m8n8.x4.trans.shared.b16 {%0,%1,%2,%3}, [%4];"
                 : "=r"(r[0]), "=r"(r[1]), "=r"(r[2]), "=r"(r[3]) : "r"(addr));
}

__device__ __forceinline__ void cpa16(uint32_t dst, const uint32_t* src) {
    asm volatile("cp.async.cg.shared.global [%0], [%1], 16;" :: "r"(dst), "l"(src));
}

__device__ __forceinline__ uint32_t s2u(const void* p) {
    uint32_t a;
    asm("{ .reg .u64 t; cvta.to.shared.u64 t, %1; cvt.u32.u64 %0, t; }"
        : "=r"(a) : "l"(p));
    return a;
}

// 2^x on a packed half2 (one MUFU for two values)
__device__ __forceinline__ uint32_t ex2h2(uint32_t x) {
    asm("ex2.approx.f16x2 %0, %0;" : "+r"(x));
    return x;
}

// ---------------------------------------------------------------------------
// fp32 -> packed half2, all three operands in ONE launch
// ---------------------------------------------------------------------------
#define XW (MTOT * CC)
#define QW (3 * CC * CC)
__global__ void cvt_all(const float* __restrict__ x,
                        const float* __restrict__ wqkv,
                        const float* __restrict__ wp) {
    int i = (blockIdx.x * 256 + threadIdx.x) * 4;
    const float* src;
    uint32_t* dst;
    if (i < XW) {
        src = x; dst = g_xh;
    } else if (i < XW + QW) {
        i -= XW; src = wqkv; dst = g_wqkvh;
    } else {
        i -= XW + QW; src = wp; dst = g_wph;
    }
    float4 v = *(const float4*)(src + i);
    *(uint2*)(dst + i / 2) = make_uint2(packh2(v.x, v.y), packh2(v.z, v.w));
}

// ---------------------------------------------------------------------------
// fp16 GEMM: BM=BN=128, BK=32 words (64 halves); 128 threads (4 warps),
// warp tile 64x64. 2-stage cp.async double buffer, ONE sync per BK step
// (16 barriers total instead of 32). 4 x k16 sub-steps between barriers.
// MODE 0: A=g_xh, W=g_wqkvh -> scatter halves into g_qh/g_kh/g_vh
//         (q scaled by SCALE*LOG2E so attention works in log2 domain)
// MODE 1: A=g_oh, W=g_wph   -> fp32 out + bias
// ---------------------------------------------------------------------------
#define SA 36                       // row stride (words): 36 % 32 == 4 phase
#define STG_W (128 * SA)            // words per stage per array (4608)
#define GEMM_SMEM (2 * STG_W * 2 * 4)   // 73,728 B -> 2 CTAs/SM

template <int MODE>
__global__ __launch_bounds__(128, 2)
void gemm_h(const float* __restrict__ bias, float* __restrict__ out) {
    extern __shared__ uint32_t dsm[];
    uint32_t* As = dsm;                 // 2 stages
    uint32_t* Bsm = dsm + 2 * STG_W;    // 2 stages

    const uint32_t* A = (MODE == 0) ? g_xh : g_oh;
    const uint32_t* W = (MODE == 0) ? g_wqkvh : g_wph;
    const int tileN = blockIdx.x * 128;
    const int tileM = blockIdx.y * 128;

    const int tid = threadIdx.x, warp = tid >> 5, lane = tid & 31;
    const int g = lane >> 2, t = lane & 3;
    const int li = lane >> 3, l8 = lane & 7;
    const int wm = (warp & 1) * 64, wn = (warp >> 1) * 64;
    const int lrow = tid >> 2;          // 0..31
    const int lch = (tid & 3) * 8;      // word offset 0,8,16,24

    const uint32_t* Ap = A + (size_t)(tileM + lrow) * CH + lch;
    const uint32_t* Wp = W + (size_t)(tileN + lrow) * CH + lch;
    const uint32_t Asb = s2u(As), Bsb = s2u(Bsm);

    // ldmatrix lane offsets (bytes, within one stage)
    const uint32_t aoff = ((wm + (li & 1) * 8 + l8) * SA + (li >> 1) * 4) * 4;
    const uint32_t boff = ((wn + (li >> 1) * 8 + l8) * SA + (li & 1) * 4) * 4;

    auto issue = [&](int s) {
        uint32_t st = (uint32_t)(s & 1) * (STG_W * 4);
        int off = s * 32;
#pragma unroll
        for (int i = 0; i < 4; i++) {
            uint32_t d = st + (uint32_t)((lrow + i * 32) * SA + lch) * 4;
            const uint32_t* ap = Ap + (size_t)(i * 32) * CH + off;
            const uint32_t* wp = Wp + (size_t)(i * 32) * CH + off;
            cpa16(Asb + d, ap);
            cpa16(Asb + d + 16, ap + 4);
            cpa16(Bsb + d, wp);
            cpa16(Bsb + d + 16, wp + 4);
        }
        asm volatile("cp.async.commit_group;");
    };

    float acc[4][8][4];
#pragma unroll
    for (int im = 0; im < 4; im++)
#pragma unroll
        for (int jn = 0; jn < 8; jn++)
#pragma unroll
            for (int c = 0; c < 4; c++) acc[im][jn][c] = 0.f;

    issue(0);

#pragma unroll 1
    for (int kt = 0; kt < 16; kt++) {
        asm volatile("cp.async.wait_group 0;");
        __syncthreads();   // stage kt visible; all warps past compute(kt-1)
        if (kt < 15) issue(kt + 1);   // writes opposite stage (read in kt-1, safe)

        const uint32_t Acb = Asb + (uint32_t)(kt & 1) * (STG_W * 4);
        const uint32_t Bcb = Bsb + (uint32_t)(kt & 1) * (STG_W * 4);
#pragma unroll
        for (int ks = 0; ks < 4; ks++) {   // 4 x k16 per stage
            const uint32_t kb = ks * 8 * 4;
            uint32_t af[4][4], bf[8][2];
#pragma unroll
            for (int im = 0; im < 4; im++)
                ldmx4(af[im], Acb + aoff + (uint32_t)(im * 16 * SA) * 4 + kb);
#pragma unroll
            for (int p = 0; p < 4; p++) {
                uint32_t q[4];
                ldmx4(q, Bcb + boff + (uint32_t)(p * 16 * SA) * 4 + kb);
                bf[2 * p][0] = q[0]; bf[2 * p][1] = q[1];
                bf[2 * p + 1][0] = q[2]; bf[2 * p + 1][1] = q[3];
            }
#pragma unroll
            for (int im = 0; im < 4; im++)
#pragma unroll
                for (int jn = 0; jn < 8; jn++) mma16(acc[im][jn], af[im], bf[jn]);
        }
    }

    if (MODE == 0) {
        const int colbase = tileN + wn;           // multiple of 64
        const int which = colbase >> 10;          // 0=q 1=k 2=v
        const int h = (colbase >> 6) & (HH - 1);
        uint32_t* dst = (which == 0) ? g_qh : (which == 1) ? g_kh : g_vh;
        const float sc = (which == 0) ? (SCALE * LOG2E) : 1.0f;
#pragma unroll
        for (int im = 0; im < 4; im++) {
            int r0 = tileM + wm + im * 16 + g;
#pragma unroll
            for (int rr = 0; rr < 2; rr++) {
                int row = r0 + rr * 8;
                int b = row >> 9, n = row & (NN - 1);
                uint32_t* dp = dst + ((size_t)(b * HH + h) * NN + n) * (HD / 2);
#pragma unroll
                for (int jn = 0; jn < 8; jn++)
                    dp[jn * 4 + t] = packh2(acc[im][jn][rr * 2 + 0] * sc,
                                            acc[im][jn][rr * 2 + 1] * sc);
            }
        }
    } else {
#pragma unroll
        for (int jn = 0; jn < 8; jn++) {
            int col = tileN + wn + jn * 8 + 2 * t;
            float2 bi = *(const float2*)(bias + col);
#pragma unroll
            for (int im = 0; im < 4; im++) {
                int r0 = tileM + wm + im * 16 + g;
                float2 v0 = make_float2(acc[im][jn][0] + bi.x, acc[im][jn][1] + bi.y);
                float2 v1 = make_float2(acc[im][jn][2] + bi.x, acc[im][jn][3] + bi.y);
                *(float2*)(out + (size_t)r0 * CC + col) = v0;
                *(float2*)(out + (size_t)(r0 + 8) * CC + col) = v1;
            }
        }
    }
}

// ---------------------------------------------------------------------------
// Flash attention (R12 version, validated): log2-domain softmax without max
// subtraction; pairwise ex2.approx.f16x2; P in registers; cp.async K/V.
// ---------------------------------------------------------------------------
#define QT 128
#define QLD 36
#define KLD 36
#define VLD 36
#define KVSTG (64 * KLD)              // words per K (or V) stage

#define AQ_OFF 0
#define AK_OFF (AQ_OFF + QT * QLD)    // 2 stages
#define AV_OFF (AK_OFF + 2 * KVSTG)   // 2 stages
#define AMK_OFF (AV_OFF + 2 * KVSTG)
#define ATTN_WORDS (AMK_OFF + 512)
#define ATTN_SMEM (ATTN_WORDS * 4)    // 57,344 B

__global__ __launch_bounds__(256, 2)
void attn_flash(const float* __restrict__ mask) {
    extern __shared__ uint32_t sm[];
    uint32_t* Qs = sm + AQ_OFF;
    float* mk = (float*)(sm + AMK_OFF);

    const int bh = blockIdx.y, b = bh >> 4, h = bh & (HH - 1);
    const int q0 = blockIdx.x * QT;
    const int tid = threadIdx.x, warp = tid >> 5, lane = tid & 31;
    const int g = lane >> 2, t = lane & 3;
    const int li = lane >> 3, l8 = lane & 7;
    const int wr = warp * 16;

    const uint32_t* qg = g_qh + (size_t)bh * NN * (HD / 2);
    const uint32_t* kg = g_kh + (size_t)bh * NN * (HD / 2);
    const uint32_t* vg = g_vh + (size_t)bh * NN * (HD / 2);

    const uint32_t Qsb = s2u(sm) + AQ_OFF * 4;
    const uint32_t Ksb = s2u(sm) + AK_OFF * 4;
    const uint32_t Vsb = s2u(sm) + AV_OFF * 4;

    const uint32_t qoff = ((wr + (li & 1) * 8 + l8) * QLD + (li >> 1) * 4) * 4;
    const uint32_t koff = (((li >> 1) * 8 + l8) * KLD + (li & 1) * 4) * 4;
    const uint32_t voff = (((li & 1) * 8 + l8) * VLD) * 4 + (li >> 1) * 16;

    const int krr = tid >> 2, kcc = (tid & 3) * 8;
    auto issue_kv = [&](int kt) {
        uint32_t st = (uint32_t)(kt & 1) * (KVSTG * 4);
        const uint32_t* ksrc = kg + (size_t)(kt * 64 + krr) * (HD / 2) + kcc;
        const uint32_t* vsrc = vg + (size_t)(kt * 64 + krr) * (HD / 2) + kcc;
        uint32_t dk = Ksb + st + (uint32_t)(krr * KLD + kcc) * 4;
        uint32_t dv = Vsb + st + (uint32_t)(krr * VLD + kcc) * 4;
        cpa16(dk, ksrc);
        cpa16(dk + 16, ksrc + 4);
        cpa16(dv, vsrc);
        cpa16(dv + 16, vsrc + 4);
        asm volatile("cp.async.commit_group;");
    };

    issue_kv(0);

    // mask pre-scaled by log2(e): softmax runs entirely in log2 domain
    for (int i = tid; i < NN; i += 256) mk[i] = mask[b * NN + i] * LOG2E;
    {   // Q tile: 128 rows x 32 words
        int r = tid >> 1, c = (tid & 1) * 16;
        const uint32_t* src = qg + (size_t)(q0 + r) * (HD / 2) + c;
        uint32_t* dst = Qs + r * QLD + c;
#pragma unroll
        for (int p = 0; p < 4; p++)
            *(uint4*)(dst + p * 4) = *(const uint4*)(src + p * 4);
    }

    float l_acc[2] = {0.f, 0.f};
    float o[8][4];
#pragma unroll
    for (int jn = 0; jn < 8; jn++)
#pragma unroll
        for (int c = 0; c < 4; c++) o[jn][c] = 0.f;

#pragma unroll 1
    for (int kt = 0; kt < 8; kt++) {
        asm volatile("cp.async.wait_group 0;");
        __syncthreads();   // stage kt visible; all warps done with kt-1; Q/mk ready
        if (kt < 7) issue_kv(kt + 1);

        const uint32_t Kcb = Ksb + (uint32_t)(kt & 1) * (KVSTG * 4);
        const uint32_t Vcb = Vsb + (uint32_t)(kt & 1) * (KVSTG * 4);

        // ---- S = Q K^T (log2-domain scores; q pre-scaled) ----
        float accs[8][4];
#pragma unroll
        for (int jn = 0; jn < 8; jn++)
#pragma unroll
            for (int c = 0; c < 4; c++) accs[jn][c] = 0.f;

#pragma unroll
        for (int ks = 0; ks < 4; ks++) {
            const uint32_t kb = ks * 8 * 4;
            uint32_t af[4], bf[8][2];
            ldmx4(af, Qsb + qoff + kb);
#pragma unroll
            for (int p = 0; p < 4; p++) {
                uint32_t q[4];
                ldmx4(q, Kcb + koff + (uint32_t)(p * 16 * KLD) * 4 + kb);
                bf[2 * p][0] = q[0]; bf[2 * p][1] = q[1];
                bf[2 * p + 1][0] = q[2]; bf[2 * p + 1][1] = q[3];
            }
#pragma unroll
            for (int jn = 0; jn < 8; jn++) mma16(accs[jn], af, bf[jn]);
        }

        // ---- p = 2^(s + mk), pairwise fp16 ex2; l from actual fp16 p ----
        uint32_t ph[8][2];
        float ts0 = 0.f, ts1 = 0.f;
#pragma unroll
        for (int jn = 0; jn < 8; jn++) {
            int col = kt * 64 + jn * 8 + 2 * t;
            float mk0 = mk[col], mk1 = mk[col + 1];
            uint32_t p01 = ex2h2(packh2(accs[jn][0] + mk0, accs[jn][1] + mk1));
            uint32_t p23 = ex2h2(packh2(accs[jn][2] + mk0, accs[jn][3] + mk1));
            ph[jn][0] = p01;
            ph[jn][1] = p23;
            float2 f01 = __half22float2(*(__half2*)&p01);
            float2 f23 = __half22float2(*(__half2*)&p23);
            ts0 += f01.x + f01.y;
            ts1 += f23.x + f23.y;
        }
        l_acc[0] += ts0;
        l_acc[1] += ts1;

        // ---- O += P V : P fragments straight from registers ----
#pragma unroll
        for (int ks = 0; ks < 4; ks++) {
            uint32_t pa[4];
            pa[0] = ph[2 * ks][0];
            pa[1] = ph[2 * ks][1];
            pa[2] = ph[2 * ks + 1][0];
            pa[3] = ph[2 * ks + 1][1];
            const uint32_t vrow = Vcb + voff + (uint32_t)(ks * 16 * VLD) * 4;
#pragma unroll
            for (int p = 0; p < 4; p++) {
                uint32_t q[4];
                ldmx4t(q, vrow + p * 32);
                uint32_t b0[2] = {q[0], q[1]};
                uint32_t b1[2] = {q[2], q[3]};
                mma16(o[2 * p], pa, b0);
                mma16(o[2 * p + 1], pa, b1);
            }
        }
    }

    // ---- reduce l across the 4 t-lanes (disjoint column subsets) once ----
#pragma unroll
    for (int d = 1; d < 4; d <<= 1) {
        l_acc[0] += __shfl_xor_sync(0xffffffffu, l_acc[0], d);
        l_acc[1] += __shfl_xor_sync(0xffffffffu, l_acc[1], d);
    }

    // ---- epilogue: normalize, pack half2 -> g_oh [B*N, CH] ----
    float inv0 = 1.0f / l_acc[0], inv1 = 1.0f / l_acc[1];
    uint32_t* og = g_oh + (size_t)(b * NN + q0 + wr + g) * CH + h * (HD / 2);
#pragma unroll
    for (int jn = 0; jn < 8; jn++) {
        og[jn * 4 + t] = packh2(o[jn][0] * inv0, o[jn][1] * inv0);
        og[(size_t)8 * CH + jn * 4 + t] = packh2(o[jn][2] * inv1, o[jn][3] * inv1);
    }
}

// ---------------------------------------------------------------------------
extern "C" void kernel_launch(void* const* d_in, const int* in_sizes, int n_in,
                              void* d_out, int out_size) {
    const float* x = (const float*)d_in[0];       // [B,N,C]
    const float* mask = (const float*)d_in[1];    // [B,N]
    const float* W_qkv = (const float*)d_in[2];   // [3C,C]
    const float* W_proj = (const float*)d_in[3];  // [C,C]
    const float* b_proj = (const float*)d_in[4];  // [C]
    float* out = (float*)d_out;                   // [B,N,C]

    static bool once = false;
    if (!once) {
        cudaFuncSetAttribute(attn_flash, cudaFuncAttributeMaxDynamicSharedMemorySize,
                             ATTN_SMEM);
        cudaFuncSetAttribute(gemm_h<0>, cudaFuncAttributeMaxDynamicSharedMemorySize,
                             GEMM_SMEM);
        cudaFuncSetAttribute(gemm_h<1>, cudaFuncAttributeMaxDynamicSharedMemorySize,
                             GEMM_SMEM);
        once = true;
    }

    cvt_all<<<(XW + QW + CC * CC) / 1024, 256>>>(x, W_qkv, W_proj);

    gemm_h<0><<<dim3(3 * CC / 128, MTOT / 128), 128, GEMM_SMEM>>>(nullptr, nullptr);
    attn_flash<<<dim3(NN / QT, BB * HH), 256, ATTN_SMEM>>>(mask);
    gemm_h<1><<<dim3(CC / 128, MTOT / 128), 128, GEMM_SMEM>>>(b_proj, out);
}

// round 14
// speedup vs baseline: 1.1247x; 1.1247x over previous
#include <cuda_runtime.h>
#include <cuda_fp16.h>
#include <cstdint>

#define BB 32
#define NN 512
#define CC 1024
#define HH 16
#define HD 64
#define SCALE 0.125f
#define LOG2E 1.44269504f
#define MTOT (BB * NN)   // 16384
#define CH (CC / 2)      // 512 packed half2 words per row

// packed-half2 scratch (uint32 = 2 fp16)
__device__ uint32_t g_xh[MTOT * CH];
__device__ uint32_t g_wqkvh[3 * CC * CH];
__device__ uint32_t g_wph[CC * CH];
__device__ uint32_t g_qh[BB * HH * NN * HD / 2];
__device__ uint32_t g_kh[BB * HH * NN * HD / 2];
__device__ uint32_t g_vh[BB * HH * NN * HD / 2];
__device__ uint32_t g_oh[MTOT * CH];

__device__ __forceinline__ uint32_t packh2(float a, float b) {
    __half2 h = __floats2half2_rn(a, b);
    return *(uint32_t*)&h;
}

__device__ __forceinline__ void mma16(float* d, const uint32_t* a, const uint32_t* b) {
    asm volatile(
        "mma.sync.aligned.m16n8k16.row.col.f32.f16.f16.f32 "
        "{%0,%1,%2,%3}, {%4,%5,%6,%7}, {%8,%9}, {%0,%1,%2,%3};"
        : "+f"(d[0]), "+f"(d[1]), "+f"(d[2]), "+f"(d[3])
        : "r"(a[0]), "r"(a[1]), "r"(a[2]), "r"(a[3]), "r"(b[0]), "r"(b[1]));
}

__device__ __forceinline__ void ldmx4(uint32_t* r, uint32_t addr) {
    asm volatile("ldmatrix.sync.aligned.m8n8.x4.shared.b16 {%0,%1,%2,%3}, [%4];"
                 : "=r"(r[0]), "=r"(r[1]), "=r"(r[2]), "=r"(r[3]) : "r"(addr));
}

__device__ __forceinline__ void ldmx4t(uint32_t* r, uint32_t addr) {
    asm volatile("ldmatrix.sync.aligned.m8n8.x4.trans.shared.b16 {%0,%1,%2,%3}, [%4];"
                 : "=r"(r[0]), "=r"(r[1]), "=r"(r[2]), "=r"(r[3]) : "r"(addr));
}

__device__ __forceinline__ void cpa16(uint32_t dst, const uint32_t* src) {
    asm volatile("cp.async.cg.shared.global [%0], [%1], 16;" :: "r"(dst), "l"(src));
}

__device__ __forceinline__ uint32_t s2u(const void* p) {
    uint32_t a;
    asm("{ .reg .u64 t; cvta.to.shared.u64 t, %1; cvt.u32.u64 %0, t; }"
        : "=r"(a) : "l"(p));
    return a;
}

// 2^x on a packed half2 (one MUFU for two values)
__device__ __forceinline__ uint32_t ex2h2(uint32_t x) {
    asm("ex2.approx.f16x2 %0, %0;" : "+r"(x));
    return x;
}

// ---------------------------------------------------------------------------
// fp32 -> packed half2, all three operands in ONE launch
// ---------------------------------------------------------------------------
#define XW (MTOT * CC)
#define QW (3 * CC * CC)
__global__ void cvt_all(const float* __restrict__ x,
                        const float* __restrict__ wqkv,
                        const float* __restrict__ wp) {
    int i = (blockIdx.x * 256 + threadIdx.x) * 4;
    const float* src;
    uint32_t* dst;
    if (i < XW) {
        src = x; dst = g_xh;
    } else if (i < XW + QW) {
        i -= XW; src = wqkv; dst = g_wqkvh;
    } else {
        i -= XW + QW; src = wp; dst = g_wph;
    }
    float4 v = *(const float4*)(src + i);
    *(uint2*)(dst + i / 2) = make_uint2(packh2(v.x, v.y), packh2(v.z, v.w));
}

// ---------------------------------------------------------------------------
// fp16 GEMM (R12 ring + fragment double-buffer):
// BM=BN=128, BK=16 words; 128 threads (4 warps), warp tile 64x64.
// 4-stage cp.async ring, ONE __syncthreads per K-step; fragments for the
// second k16 sub-step are loaded while the first computes.
// MODE 0: A=g_xh, W=g_wqkvh -> scatter halves into g_qh/g_kh/g_vh
//         (q scaled by SCALE*LOG2E so attention works in log2 domain)
// MODE 1: A=g_oh, W=g_wph   -> fp32 out + bias
// ---------------------------------------------------------------------------
#define SA 20                       // row stride (words)
#define STG_W (128 * SA)            // words per stage per array (2560)
#define GEMM_SMEM (4 * STG_W * 2 * 4)   // 81920 B -> 2 CTAs/SM

template <int MODE>
__global__ __launch_bounds__(128, 2)
void gemm_h(const float* __restrict__ bias, float* __restrict__ out) {
    extern __shared__ uint32_t dsm[];
    uint32_t* As = dsm;                 // 4 stages
    uint32_t* Bsm = dsm + 4 * STG_W;    // 4 stages

    const uint32_t* A = (MODE == 0) ? g_xh : g_oh;
    const uint32_t* W = (MODE == 0) ? g_wqkvh : g_wph;
    const int tileN = blockIdx.x * 128;
    const int tileM = blockIdx.y * 128;

    const int tid = threadIdx.x, warp = tid >> 5, lane = tid & 31;
    const int g = lane >> 2, t = lane & 3;
    const int li = lane >> 3, l8 = lane & 7;
    const int wm = (warp & 1) * 64, wn = (warp >> 1) * 64;
    const int lr = tid >> 2, lc = (tid & 3) << 2;

    const uint32_t* Ap = A + (size_t)(tileM + lr) * CH + lc;
    const uint32_t* Wp = W + (size_t)(tileN + lr) * CH + lc;
    const uint32_t Asb = s2u(As), Bsb = s2u(Bsm);

    const uint32_t aoff = ((wm + (li & 1) * 8 + l8) * SA + (li >> 1) * 4) * 4;
    const uint32_t boff = ((wn + (li >> 1) * 8 + l8) * SA + (li & 1) * 4) * 4;

    auto issue = [&](int kt) {
        uint32_t st = (uint32_t)(kt & 3) * (STG_W * 4);
        int off = kt * 16;
#pragma unroll
        for (int i = 0; i < 4; i++) {
            uint32_t d = st + (uint32_t)((lr + i * 32) * SA + lc) * 4;
            cpa16(Asb + d, Ap + (size_t)(i * 32) * CH + off);
            cpa16(Bsb + d, Wp + (size_t)(i * 32) * CH + off);
        }
        asm volatile("cp.async.commit_group;");
    };

    float acc[4][8][4];
#pragma unroll
    for (int im = 0; im < 4; im++)
#pragma unroll
        for (int jn = 0; jn < 8; jn++)
#pragma unroll
            for (int c = 0; c < 4; c++) acc[im][jn][c] = 0.f;

    issue(0);
    issue(1);

    uint32_t af[2][4][4], bf[2][8][2];

    auto ldfrags = [&](uint32_t Acb, uint32_t Bcb, int ks, int buf) {
        const uint32_t kb = ks * 8 * 4;
#pragma unroll
        for (int im = 0; im < 4; im++)
            ldmx4(af[buf][im], Acb + aoff + (uint32_t)(im * 16 * SA) * 4 + kb);
#pragma unroll
        for (int p = 0; p < 4; p++) {
            uint32_t q[4];
            ldmx4(q, Bcb + boff + (uint32_t)(p * 16 * SA) * 4 + kb);
            bf[buf][2 * p][0] = q[0]; bf[buf][2 * p][1] = q[1];
            bf[buf][2 * p + 1][0] = q[2]; bf[buf][2 * p + 1][1] = q[3];
        }
    };

#pragma unroll 1
    for (int kt = 0; kt < 32; kt++) {
        if (kt < 30) {
            issue(kt + 2);
            asm volatile("cp.async.wait_group 2;");
        } else if (kt == 30) {
            asm volatile("cp.async.wait_group 1;");
        } else {
            asm volatile("cp.async.wait_group 0;");
        }
        __syncthreads();   // stage kt visible; all warps past compute(kt-1)
        const uint32_t Acb = Asb + (uint32_t)(kt & 3) * (STG_W * 4);
        const uint32_t Bcb = Bsb + (uint32_t)(kt & 3) * (STG_W * 4);

        ldfrags(Acb, Bcb, 0, 0);       // exposed load for ks=0
        ldfrags(Acb, Bcb, 1, 1);       // overlaps ks=0 compute below
#pragma unroll
        for (int ks = 0; ks < 2; ks++) {
#pragma unroll
            for (int im = 0; im < 4; im++)
#pragma unroll
                for (int jn = 0; jn < 8; jn++)
                    mma16(acc[im][jn], af[ks][im], bf[ks][jn]);
        }
    }

    if (MODE == 0) {
        const int colbase = tileN + wn;           // multiple of 64
        const int which = colbase >> 10;          // 0=q 1=k 2=v
        const int h = (colbase >> 6) & (HH - 1);
        uint32_t* dst = (which == 0) ? g_qh : (which == 1) ? g_kh : g_vh;
        const float sc = (which == 0) ? (SCALE * LOG2E) : 1.0f;
#pragma unroll
        for (int im = 0; im < 4; im++) {
            int r0 = tileM + wm + im * 16 + g;
#pragma unroll
            for (int rr = 0; rr < 2; rr++) {
                int row = r0 + rr * 8;
                int b = row >> 9, n = row & (NN - 1);
                uint32_t* dp = dst + ((size_t)(b * HH + h) * NN + n) * (HD / 2);
#pragma unroll
                for (int jn = 0; jn < 8; jn++)
                    dp[jn * 4 + t] = packh2(acc[im][jn][rr * 2 + 0] * sc,
                                            acc[im][jn][rr * 2 + 1] * sc);
            }
        }
    } else {
#pragma unroll
        for (int jn = 0; jn < 8; jn++) {
            int col = tileN + wn + jn * 8 + 2 * t;
            float2 bi = *(const float2*)(bias + col);
#pragma unroll
            for (int im = 0; im < 4; im++) {
                int r0 = tileM + wm + im * 16 + g;
                float2 v0 = make_float2(acc[im][jn][0] + bi.x, acc[im][jn][1] + bi.y);
                float2 v1 = make_float2(acc[im][jn][2] + bi.x, acc[im][jn][3] + bi.y);
                *(float2*)(out + (size_t)r0 * CC + col) = v0;
                *(float2*)(out + (size_t)(r0 + 8) * CC + col) = v1;
            }
        }
    }
}

// ---------------------------------------------------------------------------
// Flash attention (R12 version, validated): log2-domain softmax without max
// subtraction; pairwise ex2.approx.f16x2; P in registers; cp.async K/V.
// ---------------------------------------------------------------------------
#define QT 128
#define QLD 36
#define KLD 36
#define VLD 36
#define KVSTG (64 * KLD)              // words per K (or V) stage

#define AQ_OFF 0
#define AK_OFF (AQ_OFF + QT * QLD)    // 2 stages
#define AV_OFF (AK_OFF + 2 * KVSTG)   // 2 stages
#define AMK_OFF (AV_OFF + 2 * KVSTG)
#define ATTN_WORDS (AMK_OFF + 512)
#define ATTN_SMEM (ATTN_WORDS * 4)    // 57,344 B

__global__ __launch_bounds__(256, 2)
void attn_flash(const float* __restrict__ mask) {
    extern __shared__ uint32_t sm[];
    uint32_t* Qs = sm + AQ_OFF;
    float* mk = (float*)(sm + AMK_OFF);

    const int bh = blockIdx.y, b = bh >> 4, h = bh & (HH - 1);
    const int q0 = blockIdx.x * QT;
    const int tid = threadIdx.x, warp = tid >> 5, lane = tid & 31;
    const int g = lane >> 2, t = lane & 3;
    const int li = lane >> 3, l8 = lane & 7;
    const int wr = warp * 16;

    const uint32_t* qg = g_qh + (size_t)bh * NN * (HD / 2);
    const uint32_t* kg = g_kh + (size_t)bh * NN * (HD / 2);
    const uint32_t* vg = g_vh + (size_t)bh * NN * (HD / 2);

    const uint32_t Qsb = s2u(sm) + AQ_OFF * 4;
    const uint32_t Ksb = s2u(sm) + AK_OFF * 4;
    const uint32_t Vsb = s2u(sm) + AV_OFF * 4;

    const uint32_t qoff = ((wr + (li & 1) * 8 + l8) * QLD + (li >> 1) * 4) * 4;
    const uint32_t koff = (((li >> 1) * 8 + l8) * KLD + (li & 1) * 4) * 4;
    const uint32_t voff = (((li & 1) * 8 + l8) * VLD) * 4 + (li >> 1) * 16;

    const int krr = tid >> 2, kcc = (tid & 3) * 8;
    auto issue_kv = [&](int kt) {
        uint32_t st = (uint32_t)(kt & 1) * (KVSTG * 4);
        const uint32_t* ksrc = kg + (size_t)(kt * 64 + krr) * (HD / 2) + kcc;
        const uint32_t* vsrc = vg + (size_t)(kt * 64 + krr) * (HD / 2) + kcc;
        uint32_t dk = Ksb + st + (uint32_t)(krr * KLD + kcc) * 4;
        uint32_t dv = Vsb + st + (uint32_t)(krr * VLD + kcc) * 4;
        cpa16(dk, ksrc);
        cpa16(dk + 16, ksrc + 4);
        cpa16(dv, vsrc);
        cpa16(dv + 16, vsrc + 4);
        asm volatile("cp.async.commit_group;");
    };

    issue_kv(0);

    // mask pre-scaled by log2(e): softmax runs entirely in log2 domain
    for (int i = tid; i < NN; i += 256) mk[i] = mask[b * NN + i] * LOG2E;
    {   // Q tile: 128 rows x 32 words
        int r = tid >> 1, c = (tid & 1) * 16;
        const uint32_t* src = qg + (size_t)(q0 + r) * (HD / 2) + c;
        uint32_t* dst = Qs + r * QLD + c;
#pragma unroll
        for (int p = 0; p < 4; p++)
            *(uint4*)(dst + p * 4) = *(const uint4*)(src + p * 4);
    }

    float l_acc[2] = {0.f, 0.f};
    float o[8][4];
#pragma unroll
    for (int jn = 0; jn < 8; jn++)
#pragma unroll
        for (int c = 0; c < 4; c++) o[jn][c] = 0.f;

#pragma unroll 1
    for (int kt = 0; kt < 8; kt++) {
        asm volatile("cp.async.wait_group 0;");
        __syncthreads();   // stage kt visible; all warps done with kt-1; Q/mk ready
        if (kt < 7) issue_kv(kt + 1);

        const uint32_t Kcb = Ksb + (uint32_t)(kt & 1) * (KVSTG * 4);
        const uint32_t Vcb = Vsb + (uint32_t)(kt & 1) * (KVSTG * 4);

        // ---- S = Q K^T (log2-domain scores; q pre-scaled) ----
        float accs[8][4];
#pragma unroll
        for (int jn = 0; jn < 8; jn++)
#pragma unroll
            for (int c = 0; c < 4; c++) accs[jn][c] = 0.f;

#pragma unroll
        for (int ks = 0; ks < 4; ks++) {
            const uint32_t kb = ks * 8 * 4;
            uint32_t af[4], bf[8][2];
            ldmx4(af, Qsb + qoff + kb);
#pragma unroll
            for (int p = 0; p < 4; p++) {
                uint32_t q[4];
                ldmx4(q, Kcb + koff + (uint32_t)(p * 16 * KLD) * 4 + kb);
                bf[2 * p][0] = q[0]; bf[2 * p][1] = q[1];
                bf[2 * p + 1][0] = q[2]; bf[2 * p + 1][1] = q[3];
            }
#pragma unroll
            for (int jn = 0; jn < 8; jn++) mma16(accs[jn], af, bf[jn]);
        }

        // ---- p = 2^(s + mk), pairwise fp16 ex2; l from actual fp16 p ----
        uint32_t ph[8][2];
        float ts0 = 0.f, ts1 = 0.f;
#pragma unroll
        for (int jn = 0; jn < 8; jn++) {
            int col = kt * 64 + jn * 8 + 2 * t;
            float mk0 = mk[col], mk1 = mk[col + 1];
            uint32_t p01 = ex2h2(packh2(accs[jn][0] + mk0, accs[jn][1] + mk1));
            uint32_t p23 = ex2h2(packh2(accs[jn][2] + mk0, accs[jn][3] + mk1));
            ph[jn][0] = p01;
            ph[jn][1] = p23;
            float2 f01 = __half22float2(*(__half2*)&p01);
            float2 f23 = __half22float2(*(__half2*)&p23);
            ts0 += f01.x + f01.y;
            ts1 += f23.x + f23.y;
        }
        l_acc[0] += ts0;
        l_acc[1] += ts1;

        // ---- O += P V : P fragments straight from registers ----
#pragma unroll
        for (int ks = 0; ks < 4; ks++) {
            uint32_t pa[4];
            pa[0] = ph[2 * ks][0];
            pa[1] = ph[2 * ks][1];
            pa[2] = ph[2 * ks + 1][0];
            pa[3] = ph[2 * ks + 1][1];
            const uint32_t vrow = Vcb + voff + (uint32_t)(ks * 16 * VLD) * 4;
#pragma unroll
            for (int p = 0; p < 4; p++) {
                uint32_t q[4];
                ldmx4t(q, vrow + p * 32);
                uint32_t b0[2] = {q[0], q[1]};
                uint32_t b1[2] = {q[2], q[3]};
                mma16(o[2 * p], pa, b0);
                mma16(o[2 * p + 1], pa, b1);
            }
        }
    }

    // ---- reduce l across the 4 t-lanes (disjoint column subsets) once ----
#pragma unroll
    for (int d = 1; d < 4; d <<= 1) {
        l_acc[0] += __shfl_xor_sync(0xffffffffu, l_acc[0], d);
        l_acc[1] += __shfl_xor_sync(0xffffffffu, l_acc[1], d);
    }

    // ---- epilogue: normalize, pack half2 -> g_oh [B*N, CH] ----
    float inv0 = 1.0f / l_acc[0], inv1 = 1.0f / l_acc[1];
    uint32_t* og = g_oh + (size_t)(b * NN + q0 + wr + g) * CH + h * (HD / 2);
#pragma unroll
    for (int jn = 0; jn < 8; jn++) {
        og[jn * 4 + t] = packh2(o[jn][0] * inv0, o[jn][1] * inv0);
        og[(size_t)8 * CH + jn * 4 + t] = packh2(o[jn][2] * inv1, o[jn][3] * inv1);
    }
}

// ---------------------------------------------------------------------------
extern "C" void kernel_launch(void* const* d_in, const int* in_sizes, int n_in,
                              void* d_out, int out_size) {
    const float* x = (const float*)d_in[0];       // [B,N,C]
    const float* mask = (const float*)d_in[1];    // [B,N]
    const float* W_qkv = (const float*)d_in[2];   // [3C,C]
    const float* W_proj = (const float*)d_in[3];  // [C,C]
    const float* b_proj = (const float*)d_in[4];  // [C]
    float* out = (float*)d_out;                   // [B,N,C]

    static bool once = false;
    if (!once) {
        cudaFuncSetAttribute(attn_flash, cudaFuncAttributeMaxDynamicSharedMemorySize,
                             ATTN_SMEM);
        cudaFuncSetAttribute(gemm_h<0>, cudaFuncAttributeMaxDynamicSharedMemorySize,
                             GEMM_SMEM);
        cudaFuncSetAttribute(gemm_h<1>, cudaFuncAttributeMaxDynamicSharedMemorySize,
                             GEMM_SMEM);
        once = true;
    }

    cvt_all<<<(XW + QW + CC * CC) / 1024, 256>>>(x, W_qkv, W_proj);

    gemm_h<0><<<dim3(3 * CC / 128, MTOT / 128), 128, GEMM_SMEM>>>(nullptr, nullptr);
    attn_flash<<<dim3(NN / QT, BB * HH), 256, ATTN_SMEM>>>(mask);
    gemm_h<1><<<dim3(CC / 128, MTOT / 128), 128, GEMM_SMEM>>>(b_proj, out);
}